// round 9
// baseline (speedup 1.0000x reference)
#include <cuda_runtime.h>
#include <cstdint>

#define B 4
#define S 2048
#define D 768
#define NH 4
#define DH 192
#define KCONV 4
#define BS (B*S)

// ---------------- scratch (static device globals; no allocation) ----------------
__device__ float g_xconv[(size_t)B*S*D];        // 25 MB
__device__ float g_G[(size_t)4*B*S*D];          // 100 MB : [g][b*S+s][d]
__device__ float g_Y[(size_t)B*S*D];            // 25 MB : pre-LN hidden states

__device__ __forceinline__ void fma2(unsigned long long& acc,
                                     unsigned long long a, unsigned long long b) {
    asm volatile("fma.rn.f32x2 %0, %1, %2, %0;" : "+l"(acc) : "l"(a), "l"(b));
}
__device__ __forceinline__ float hsum2(unsigned long long a, unsigned long long b) {
    asm volatile("add.rn.f32x2 %0, %0, %1;" : "+l"(a) : "l"(b));
    float lo = __uint_as_float((unsigned)(a & 0xffffffffull));
    float hi = __uint_as_float((unsigned)(a >> 32));
    return lo + hi;
}
__device__ __forceinline__ unsigned long long pack2(float lo, float hi) {
    unsigned long long r;
    asm("mov.b64 %0, {%1, %2};" : "=l"(r)
        : "r"(__float_as_uint(lo)), "r"(__float_as_uint(hi)));
    return r;
}

// =====================================================================
// Kernel 1: causal depthwise conv1d + swish
// =====================================================================
__global__ __launch_bounds__(256) void conv_swish_kernel(
    const float* __restrict__ x, const float* __restrict__ ck,
    const float* __restrict__ cb)
{
    int idx = blockIdx.x * 256 + threadIdx.x;
    if (idx >= B*S*D) return;
    int d = idx % D;
    int s = (idx / D) % S;
    int base = idx - s*D - d;               // b*S*D
    float acc = cb[d];
    #pragma unroll
    for (int j = 0; j < KCONV; j++) {
        int ss = s - (KCONV-1) + j;
        if (ss >= 0) acc = fmaf(x[base + ss*D + d], ck[j*D + d], acc);
    }
    g_xconv[idx] = acc / (1.f + __expf(-acc));   // swish
}

// =====================================================================
// Kernel 2: block-diagonal gate projections (f32x2 inner loop)
// =====================================================================
#define GT_ROWS 64
#define IPAD 193
__global__ __launch_bounds__(256) void gate_gemm_kernel(
    const float* __restrict__ x,
    const float* __restrict__ Wi, const float* __restrict__ Wf,
    const float* __restrict__ Wz, const float* __restrict__ Wo,
    const float* __restrict__ cbias)
{
    extern __shared__ float sm[];
    float* Ws = sm;                 // [192][192] d-major rows
    float* Is = sm + 192*192;       // [64][IPAD]
    int g    = blockIdx.z;
    int hh   = blockIdx.y;
    int tile = blockIdx.x;
    const float* src = (g < 2) ? g_xconv : x;
    const float* W   = (g==0) ? Wi : (g==1) ? Wf : (g==2) ? Wz : Wo;
    int t = threadIdx.x;

    for (int i = t; i < 192*192; i += 256)
        Ws[i] = W[hh*36864 + i];
    for (int i = t; i < GT_ROWS*192; i += 256) {
        int rr = i / 192, d = i % 192;
        Is[rr*IPAD + d] = src[(size_t)(tile*GT_ROWS + rr)*D + hh*DH + d];
    }
    __syncthreads();

    int tx = t & 15;       // 4 rows each
    int ty = t >> 4;       // 12 cols each
    int e0 = ty*12;
    unsigned long long acc2[4][6];
    #pragma unroll
    for (int i = 0; i < 4; i++)
        #pragma unroll
        for (int j = 0; j < 6; j++) acc2[i][j] = 0ull;

    #pragma unroll 2
    for (int d = 0; d < 192; d++) {
        unsigned long long aa[4];
        #pragma unroll
        for (int i = 0; i < 4; i++) {
            float a = Is[(tx*4+i)*IPAD + d];
            aa[i] = pack2(a, a);
        }
        const ulonglong2* Bp = (const ulonglong2*)&Ws[d*192 + e0];
        ulonglong2 b0 = Bp[0], b1 = Bp[1], b2 = Bp[2];
        unsigned long long bb[6] = {b0.x, b0.y, b1.x, b1.y, b2.x, b2.y};
        #pragma unroll
        for (int i = 0; i < 4; i++)
            #pragma unroll
            for (int j = 0; j < 6; j++)
                fma2(acc2[i][j], aa[i], bb[j]);
    }

    #pragma unroll
    for (int i = 0; i < 4; i++) {
        size_t r = (size_t)tile*GT_ROWS + tx*4 + i;
        float* op = g_G + ((size_t)g*BS + r)*D + hh*DH + e0;
        const float* bp = cbias + g*D + hh*DH + e0;
        #pragma unroll
        for (int j = 0; j < 6; j++) {
            float lo = __uint_as_float((unsigned)(acc2[i][j] & 0xffffffffull));
            float hi = __uint_as_float((unsigned)(acc2[i][j] >> 32));
            op[2*j]   = lo + bp[2*j];
            op[2*j+1] = hi + bp[2*j+1];
        }
    }
}

// =====================================================================
// Kernel 3: sLSTM scan — 4-CTA clusters, vectorized st.async exchange.
//   cluster = (batch, head); CTA rank owns 48 e's; 384 threads.
//   Lane map: e = t>>3, g = (t>>1)&3, dc = t&1.
//   Exchange: per warp, shfl-gather 4 h values -> lane0 st.async.v4.b32
//   to each of 4 ranks (12 v4 stores in, per barrier, per step).
// =====================================================================
#define HPAD 200
#define CSZ 4
#define EPC 48            // e's per CTA
#define SCAN_T 384

__device__ __forceinline__ void mbar_wait(uint32_t bar, uint32_t parity) {
    asm volatile(
        "{\n\t"
        ".reg .pred P;\n\t"
        "WL_%=:\n\t"
        "mbarrier.try_wait.parity.acquire.cta.shared::cta.b64 P, [%0], %1, 0x989680;\n\t"
        "@!P bra WL_%=;\n\t"
        "}" :: "r"(bar), "r"(parity) : "memory");
}

__global__ void __cluster_dims__(CSZ,1,1) __launch_bounds__(SCAN_T)
scan_kernel(const float* __restrict__ Rg)
{
    __shared__ __align__(16) float h_s[2][HPAD];
    __shared__ __align__(8)  unsigned long long mbar[2];

    const int t    = threadIdx.x;
    const int cl   = blockIdx.x >> 2;     // 0..15
    const int rank = blockIdx.x & 3;
    const int hh   = cl & 3;
    const int b    = cl >> 2;
    const int e_base = rank * EPC;

    const int e  = t >> 3;          // 0..47
    const int g  = (t >> 1) & 3;
    const int dc = t & 1;
    const int d0 = dc * 96;
    const int eg = e_base + e;

    // R[g][hh][d0+2j(+1)][eg] -> packed register pairs over d
    unsigned long long Rr[48];
    {
        const float* Rp = Rg + ((size_t)(g*NH + hh)*192 + d0)*192 + eg;
        #pragma unroll
        for (int j = 0; j < 48; j++)
            Rr[j] = pack2(Rp[(2*j)*192], Rp[(2*j+1)*192]);
    }
    for (int i = t; i < 2*HPAD; i += SCAN_T) ((float*)h_s)[i] = 0.f;

    const uint32_t hbase = (uint32_t)__cvta_generic_to_shared(&h_s[0][0]);
    const uint32_t bbase = (uint32_t)__cvta_generic_to_shared(&mbar[0]);
    if (t == 0) {
        asm volatile("mbarrier.init.shared.b64 [%0], 1;" :: "r"(bbase) : "memory");
        asm volatile("mbarrier.init.shared.b64 [%0], 1;" :: "r"(bbase+8) : "memory");
        asm volatile("mbarrier.arrive.expect_tx.shared.b64 _, [%0], 768;" :: "r"(bbase)   : "memory");
        asm volatile("mbarrier.arrive.expect_tx.shared.b64 _, [%0], 768;" :: "r"(bbase+8) : "memory");
    }
    __syncthreads();
    asm volatile("barrier.cluster.arrive.aligned;" ::: "memory");
    asm volatile("barrier.cluster.wait.aligned;"   ::: "memory");

    // remote addresses: this warp's 16B h-chunk (4 consecutive e's) per buffer/rank
    const int chunk_e = e_base + ((t >> 5) << 2);   // lane0's e, 4-aligned
    uint32_t rh[2][CSZ], rb[2][CSZ];
    #pragma unroll
    for (int r = 0; r < CSZ; r++) {
        uint32_t l0 = hbase + (uint32_t)(chunk_e*4);
        uint32_t l1 = hbase + (uint32_t)((HPAD + chunk_e)*4);
        asm volatile("mapa.shared::cluster.u32 %0, %1, %2;" : "=r"(rh[0][r]) : "r"(l0), "r"(r));
        asm volatile("mapa.shared::cluster.u32 %0, %1, %2;" : "=r"(rh[1][r]) : "r"(l1), "r"(r));
        asm volatile("mapa.shared::cluster.u32 %0, %1, %2;" : "=r"(rb[0][r]) : "r"(bbase), "r"(r));
        asm volatile("mapa.shared::cluster.u32 %0, %1, %2;" : "=r"(rb[1][r]) : "r"(bbase+8u), "r"(r));
    }

    const float* gptr = g_G + ((size_t)g*BS + (size_t)b*S)*D + hh*DH + eg;
    float gc = *gptr;

    float cs = 0.f, ns = 0.f, ms = 0.f;
    uint32_t ph0 = 0u, ph1 = 0u;
    const int lbase = (t & 31) & 24;       // e-group base lane within warp
    int p = 0;

    for (int s = 0; s < S; s++) {
        // prefetch next step's gate pre-activation (overlaps wait + matvec)
        float gn = (s + 1 < S) ? __ldg(gptr + D) : 0.f;
        gptr += D;

        if (s) {
            uint32_t bar = bbase + (uint32_t)(p*8);
            uint32_t par = p ? ph1 : ph0;
            mbar_wait(bar, par);
            if (p) ph1 ^= 1u; else ph0 ^= 1u;
            if (t == 0)
                asm volatile("mbarrier.arrive.expect_tx.shared.b64 _, [%0], 768;"
                             :: "r"(bar) : "memory");
        }

        // recurrent matvec over this thread's d-half (packed f32x2)
        const ulonglong2* Hp = (const ulonglong2*)&h_s[p][d0];
        unsigned long long a0 = 0ull, a1 = 0ull;
        #pragma unroll
        for (int k = 0; k < 24; k++) {
            ulonglong2 hv = Hp[k];
            fma2(a0, Rr[2*k],   hv.x);
            fma2(a1, Rr[2*k+1], hv.y);
        }
        float v = hsum2(a0, a1);
        v += __shfl_xor_sync(0xffffffffu, v, 1);   // combine d-halves
        v += gc;                                    // full gate pre-activation
        gc = gn;

        float iv = __shfl_sync(0xffffffffu, v, lbase + 0);
        float fv = __shfl_sync(0xffffffffu, v, lbase + 2);
        float zv = __shfl_sync(0xffffffffu, v, lbase + 4);
        float ov = __shfl_sync(0xffffffffu, v, lbase + 6);

        // gating (replicated across the 8 lanes of the e-group)
        float mn = fmaxf(fv + ms, iv);
        float ia = __expf(iv - mn);
        float fa = __expf(fv + ms - mn);
        float zc = fminf(fmaxf(zv, -15.f), 15.f);
        float ez = __expf(2.f*zc);
        float th = (ez - 1.f) / (ez + 1.f);
        float cn = fa*cs + ia*th;
        float nn = fa*ns + ia;
        float sg = 1.f / (1.f + __expf(-ov));
        float hv = sg * cn / nn;
        cs = cn; ns = nn; ms = mn;

        int pw = p ^ 1;
        // gather the warp's 4 h values (lanes 0,8,16,24) into every lane
        float h1 = __shfl_sync(0xffffffffu, hv, 8);
        float h2 = __shfl_sync(0xffffffffu, hv, 16);
        float h3 = __shfl_sync(0xffffffffu, hv, 24);
        // last step: nobody reads step-S h — do NOT touch peer SMEM (exit race)
        if ((t & 31) == 0 && s + 1 < S) {
            uint32_t u0 = __float_as_uint(hv), u1 = __float_as_uint(h1);
            uint32_t u2 = __float_as_uint(h2), u3 = __float_as_uint(h3);
            #pragma unroll
            for (int r = 0; r < CSZ; r++) {
                asm volatile(
                    "st.async.shared::cluster.mbarrier::complete_tx::bytes.v4.b32 "
                    "[%0], {%1, %2, %3, %4}, [%5];"
                    :: "r"(rh[pw][r]), "r"(u0), "r"(u1), "r"(u2), "r"(u3),
                       "r"(rb[pw][r]) : "memory");
            }
        }
        if ((t & 7) == 2)
            g_Y[((size_t)b*S + s)*D + hh*DH + eg] = hv;
        p = pw;
    }

    // final guard: no CTA leaves while any peer could still have traffic here
    asm volatile("barrier.cluster.arrive.aligned;" ::: "memory");
    asm volatile("barrier.cluster.wait.aligned;"   ::: "memory");
}

// =====================================================================
// Kernel 4: per-(b,s,head) layernorm over DH=192, scaled by gn_scale
// =====================================================================
__global__ __launch_bounds__(256) void ln_kernel(
    const float* __restrict__ gscale, float* __restrict__ out)
{
    int w    = (blockIdx.x * 256 + threadIdx.x) >> 5;   // global warp id
    int lane = threadIdx.x & 31;
    if (w >= BS*NH) return;
    int r  = w >> 2;          // b*S+s
    int hh = w & 3;
    const float* yp = g_Y + (size_t)r*D + hh*DH;
    float v[6]; float sum = 0.f, sq = 0.f;
    #pragma unroll
    for (int k = 0; k < 6; k++) {
        v[k] = yp[lane + 32*k];
        sum += v[k]; sq = fmaf(v[k], v[k], sq);
    }
    #pragma unroll
    for (int o = 16; o; o >>= 1) {
        sum += __shfl_xor_sync(0xffffffffu, sum, o);
        sq  += __shfl_xor_sync(0xffffffffu, sq,  o);
    }
    float mu  = sum * (1.f/192.f);
    float var = sq * (1.f/192.f) - mu*mu;
    float inv = rsqrtf(var + 1e-5f);
    float* op = out + (size_t)r*D + hh*DH;
    #pragma unroll
    for (int k = 0; k < 6; k++)
        op[lane + 32*k] = (v[k] - mu) * inv * gscale[hh*DH + lane + 32*k];
}

// =====================================================================
extern "C" void kernel_launch(void* const* d_in, const int* in_sizes, int n_in,
                              void* d_out, int out_size)
{
    const float* x     = (const float*)d_in[0];
    const float* ck    = (const float*)d_in[1];
    const float* cb    = (const float*)d_in[2];
    const float* Wi    = (const float*)d_in[3];
    const float* Wf    = (const float*)d_in[4];
    const float* Wz    = (const float*)d_in[5];
    const float* Wo    = (const float*)d_in[6];
    const float* R     = (const float*)d_in[7];
    const float* cbias = (const float*)d_in[8];
    const float* gs    = (const float*)d_in[9];
    float* out = (float*)d_out;

    conv_swish_kernel<<<(B*S*D + 255)/256, 256>>>(x, ck, cb);

    size_t gemm_smem = (size_t)(192*192 + GT_ROWS*IPAD) * sizeof(float);
    cudaFuncSetAttribute(gate_gemm_kernel,
                         cudaFuncAttributeMaxDynamicSharedMemorySize, (int)gemm_smem);
    dim3 ggrid(BS/GT_ROWS, NH, 4);
    gate_gemm_kernel<<<ggrid, 256, gemm_smem>>>(x, Wi, Wf, Wz, Wo, cbias);

    scan_kernel<<<64, SCAN_T>>>(R);

    ln_kernel<<<(BS*NH*32 + 255)/256, 256>>>(gs, out);
}

// round 10
// speedup vs baseline: 1.1051x; 1.1051x over previous
#include <cuda_runtime.h>
#include <cstdint>

#define B 4
#define S 2048
#define D 768
#define NH 4
#define DH 192
#define KCONV 4
#define BS (B*S)

// ---------------- scratch (static device globals; no allocation) ----------------
__device__ float g_xconv[(size_t)B*S*D];        // 25 MB
__device__ float g_G[(size_t)4*B*S*D];          // 100 MB : [g][b*S+s][d]
__device__ float g_Y[(size_t)B*S*D];            // 25 MB : pre-LN hidden states

__device__ __forceinline__ void fma2(unsigned long long& acc,
                                     unsigned long long a, unsigned long long b) {
    asm volatile("fma.rn.f32x2 %0, %1, %2, %0;" : "+l"(acc) : "l"(a), "l"(b));
}
__device__ __forceinline__ float hsum2(unsigned long long a, unsigned long long b) {
    asm volatile("add.rn.f32x2 %0, %0, %1;" : "+l"(a) : "l"(b));
    float lo = __uint_as_float((unsigned)(a & 0xffffffffull));
    float hi = __uint_as_float((unsigned)(a >> 32));
    return lo + hi;
}
__device__ __forceinline__ unsigned long long pack2(float lo, float hi) {
    unsigned long long r;
    asm("mov.b64 %0, {%1, %2};" : "=l"(r)
        : "r"(__float_as_uint(lo)), "r"(__float_as_uint(hi)));
    return r;
}

// =====================================================================
// Kernel 1: causal depthwise conv1d + swish
// =====================================================================
__global__ __launch_bounds__(256) void conv_swish_kernel(
    const float* __restrict__ x, const float* __restrict__ ck,
    const float* __restrict__ cb)
{
    int idx = blockIdx.x * 256 + threadIdx.x;
    if (idx >= B*S*D) return;
    int d = idx % D;
    int s = (idx / D) % S;
    int base = idx - s*D - d;               // b*S*D
    float acc = cb[d];
    #pragma unroll
    for (int j = 0; j < KCONV; j++) {
        int ss = s - (KCONV-1) + j;
        if (ss >= 0) acc = fmaf(x[base + ss*D + d], ck[j*D + d], acc);
    }
    g_xconv[idx] = acc / (1.f + __expf(-acc));   // swish
}

// =====================================================================
// Kernel 2: block-diagonal gate projections (f32x2 inner loop)
// =====================================================================
#define GT_ROWS 64
#define IPAD 193
__global__ __launch_bounds__(256) void gate_gemm_kernel(
    const float* __restrict__ x,
    const float* __restrict__ Wi, const float* __restrict__ Wf,
    const float* __restrict__ Wz, const float* __restrict__ Wo,
    const float* __restrict__ cbias)
{
    extern __shared__ float sm[];
    float* Ws = sm;                 // [192][192] d-major rows
    float* Is = sm + 192*192;       // [64][IPAD]
    int g    = blockIdx.z;
    int hh   = blockIdx.y;
    int tile = blockIdx.x;
    const float* src = (g < 2) ? g_xconv : x;
    const float* W   = (g==0) ? Wi : (g==1) ? Wf : (g==2) ? Wz : Wo;
    int t = threadIdx.x;

    for (int i = t; i < 192*192; i += 256)
        Ws[i] = W[hh*36864 + i];
    for (int i = t; i < GT_ROWS*192; i += 256) {
        int rr = i / 192, d = i % 192;
        Is[rr*IPAD + d] = src[(size_t)(tile*GT_ROWS + rr)*D + hh*DH + d];
    }
    __syncthreads();

    int tx = t & 15;       // 4 rows each
    int ty = t >> 4;       // 12 cols each
    int e0 = ty*12;
    unsigned long long acc2[4][6];
    #pragma unroll
    for (int i = 0; i < 4; i++)
        #pragma unroll
        for (int j = 0; j < 6; j++) acc2[i][j] = 0ull;

    #pragma unroll 2
    for (int d = 0; d < 192; d++) {
        unsigned long long aa[4];
        #pragma unroll
        for (int i = 0; i < 4; i++) {
            float a = Is[(tx*4+i)*IPAD + d];
            aa[i] = pack2(a, a);
        }
        const ulonglong2* Bp = (const ulonglong2*)&Ws[d*192 + e0];
        ulonglong2 b0 = Bp[0], b1 = Bp[1], b2 = Bp[2];
        unsigned long long bb[6] = {b0.x, b0.y, b1.x, b1.y, b2.x, b2.y};
        #pragma unroll
        for (int i = 0; i < 4; i++)
            #pragma unroll
            for (int j = 0; j < 6; j++)
                fma2(acc2[i][j], aa[i], bb[j]);
    }

    #pragma unroll
    for (int i = 0; i < 4; i++) {
        size_t r = (size_t)tile*GT_ROWS + tx*4 + i;
        float* op = g_G + ((size_t)g*BS + r)*D + hh*DH + e0;
        const float* bp = cbias + g*D + hh*DH + e0;
        #pragma unroll
        for (int j = 0; j < 6; j++) {
            float lo = __uint_as_float((unsigned)(acc2[i][j] & 0xffffffffull));
            float hi = __uint_as_float((unsigned)(acc2[i][j] >> 32));
            op[2*j]   = lo + bp[2*j];
            op[2*j+1] = hi + bp[2*j+1];
        }
    }
}

// =====================================================================
// Kernel 3: sLSTM scan — R7 structure (8-CTA clusters, scalar st.async)
//   + depth-4 register-ring G prefetch + fast-math gating.
// =====================================================================
#define HPAD 200

__device__ __forceinline__ void mbar_wait(uint32_t bar, uint32_t parity) {
    asm volatile(
        "{\n\t"
        ".reg .pred P;\n\t"
        "WL_%=:\n\t"
        "mbarrier.try_wait.parity.acquire.cta.shared::cta.b64 P, [%0], %1, 0x989680;\n\t"
        "@!P bra WL_%=;\n\t"
        "}" :: "r"(bar), "r"(parity) : "memory");
}

__global__ void __cluster_dims__(8,1,1) __launch_bounds__(192)
scan_kernel(const float* __restrict__ Rg)
{
    __shared__ __align__(16) float h_s[2][HPAD];
    __shared__ __align__(8)  unsigned long long mbar[2];

    const int t    = threadIdx.x;
    const int cl   = blockIdx.x >> 3;     // 0..15
    const int rank = blockIdx.x & 7;
    const int hh   = cl & 3;
    const int b    = cl >> 2;
    const int e_base = rank * 24;

    const int e  = t >> 3;          // 0..23
    const int g  = (t >> 1) & 3;
    const int dc = t & 1;
    const int d0 = dc * 96;
    const int eg = e_base + e;

    // R[g][hh][d0+2j(+1)][eg] -> packed register pairs over d
    unsigned long long Rr[48];
    {
        const float* Rp = Rg + ((size_t)(g*NH + hh)*192 + d0)*192 + eg;
        #pragma unroll
        for (int j = 0; j < 48; j++)
            Rr[j] = pack2(Rp[(2*j)*192], Rp[(2*j+1)*192]);
    }
    for (int i = t; i < 2*HPAD; i += 192) ((float*)h_s)[i] = 0.f;

    const uint32_t hbase = (uint32_t)__cvta_generic_to_shared(&h_s[0][0]);
    const uint32_t bbase = (uint32_t)__cvta_generic_to_shared(&mbar[0]);
    if (t == 0) {
        asm volatile("mbarrier.init.shared.b64 [%0], 1;" :: "r"(bbase) : "memory");
        asm volatile("mbarrier.init.shared.b64 [%0], 1;" :: "r"(bbase+8) : "memory");
        asm volatile("mbarrier.arrive.expect_tx.shared.b64 _, [%0], 768;" :: "r"(bbase)   : "memory");
        asm volatile("mbarrier.arrive.expect_tx.shared.b64 _, [%0], 768;" :: "r"(bbase+8) : "memory");
    }
    __syncthreads();
    asm volatile("barrier.cluster.arrive.aligned;" ::: "memory");
    asm volatile("barrier.cluster.wait.aligned;"   ::: "memory");

    // precompute remote addresses (per buffer, per rank)
    uint32_t rh[2][8], rb[2][8];
    #pragma unroll
    for (int r = 0; r < 8; r++) {
        uint32_t l0 = hbase + (uint32_t)(eg*4);
        uint32_t l1 = hbase + (uint32_t)((HPAD + eg)*4);
        asm volatile("mapa.shared::cluster.u32 %0, %1, %2;" : "=r"(rh[0][r]) : "r"(l0), "r"(r));
        asm volatile("mapa.shared::cluster.u32 %0, %1, %2;" : "=r"(rh[1][r]) : "r"(l1), "r"(r));
        asm volatile("mapa.shared::cluster.u32 %0, %1, %2;" : "=r"(rb[0][r]) : "r"(bbase), "r"(r));
        asm volatile("mapa.shared::cluster.u32 %0, %1, %2;" : "=r"(rb[1][r]) : "r"(bbase+8u), "r"(r));
    }

    const float* gbase = g_G + ((size_t)g*BS + (size_t)b*S)*D + hh*DH + eg;

    // depth-4 G prefetch ring: gring[k] holds gate preact for step sb+k
    float gring[4];
    #pragma unroll
    for (int k = 0; k < 4; k++) gring[k] = __ldg(gbase + (size_t)k*D);
    const float* gpf = gbase + (size_t)4*D;    // next address to prefetch (s+4)

    float cs = 0.f, ns = 0.f, ms = 0.f;
    uint32_t ph0 = 0u, ph1 = 0u;
    const int lbase = (t & 31) & 24;       // e-group base lane within warp

    for (int sb = 0; sb < S; sb += 4) {
        #pragma unroll
        for (int k = 0; k < 4; k++) {
            const int s = sb + k;
            const int p  = k & 1;          // since S steps alternate and sb is even
            const int pw = p ^ 1;

            float gc = gring[k];
            // prefetch for step s+4 (4 step-times of latency slack)
            gring[k] = (s + 4 < S) ? __ldg(gpf) : 0.f;
            gpf += D;

            if (sb || k) {
                uint32_t bar = bbase + (uint32_t)(p*8);
                uint32_t par = p ? ph1 : ph0;
                mbar_wait(bar, par);
                if (p) ph1 ^= 1u; else ph0 ^= 1u;
                if (t == 0)
                    asm volatile("mbarrier.arrive.expect_tx.shared.b64 _, [%0], 768;"
                                 :: "r"(bar) : "memory");
            }

            // recurrent matvec over this thread's d-half (packed f32x2)
            const ulonglong2* Hp = (const ulonglong2*)&h_s[p][d0];
            unsigned long long a0 = 0ull, a1 = 0ull;
            #pragma unroll
            for (int kk = 0; kk < 24; kk++) {
                ulonglong2 hv2 = Hp[kk];
                fma2(a0, Rr[2*kk],   hv2.x);
                fma2(a1, Rr[2*kk+1], hv2.y);
            }
            float v = hsum2(a0, a1);
            v += __shfl_xor_sync(0xffffffffu, v, 1);   // combine d-halves
            v += gc;                                    // full gate pre-activation

            float iv = __shfl_sync(0xffffffffu, v, lbase + 0);
            float fv = __shfl_sync(0xffffffffu, v, lbase + 2);
            float zv = __shfl_sync(0xffffffffu, v, lbase + 4);
            float ov = __shfl_sync(0xffffffffu, v, lbase + 6);

            // gating (replicated across the 8 lanes of the e-group), fast math
            float mn = fmaxf(fv + ms, iv);
            float ia = __expf(iv - mn);
            float fa = __expf(fv + ms - mn);
            float zc = fminf(fmaxf(zv, -15.f), 15.f);
            float ez = __expf(2.f*zc);
            float th = 1.f - __fdividef(2.f, ez + 1.f);
            float cn = fa*cs + ia*th;
            float nn = fa*ns + ia;
            float sg = __fdividef(1.f, 1.f + __expf(-ov));
            float hv = sg * __fdividef(cn, nn);
            cs = cn; ns = nn; ms = mn;

            // last step: nobody reads step-S h — do NOT touch peer SMEM
            if ((t & 7) == 0 && s + 1 < S) {
                uint32_t hu = __float_as_uint(hv);
                #pragma unroll
                for (int r = 0; r < 8; r++) {
                    asm volatile(
                        "st.async.shared::cluster.mbarrier::complete_tx::bytes.b32 [%0], %1, [%2];"
                        :: "r"(rh[pw][r]), "r"(hu), "r"(rb[pw][r]) : "memory");
                }
            }
            if ((t & 7) == 2)
                g_Y[((size_t)b*S + s)*D + hh*DH + eg] = hv;
        }
    }

    // final guard: no CTA leaves while any peer could still have traffic here
    asm volatile("barrier.cluster.arrive.aligned;" ::: "memory");
    asm volatile("barrier.cluster.wait.aligned;"   ::: "memory");
}

// =====================================================================
// Kernel 4: per-(b,s,head) layernorm over DH=192, scaled by gn_scale
// =====================================================================
__global__ __launch_bounds__(256) void ln_kernel(
    const float* __restrict__ gscale, float* __restrict__ out)
{
    int w    = (blockIdx.x * 256 + threadIdx.x) >> 5;   // global warp id
    int lane = threadIdx.x & 31;
    if (w >= BS*NH) return;
    int r  = w >> 2;          // b*S+s
    int hh = w & 3;
    const float* yp = g_Y + (size_t)r*D + hh*DH;
    float v[6]; float sum = 0.f, sq = 0.f;
    #pragma unroll
    for (int k = 0; k < 6; k++) {
        v[k] = yp[lane + 32*k];
        sum += v[k]; sq = fmaf(v[k], v[k], sq);
    }
    #pragma unroll
    for (int o = 16; o; o >>= 1) {
        sum += __shfl_xor_sync(0xffffffffu, sum, o);
        sq  += __shfl_xor_sync(0xffffffffu, sq,  o);
    }
    float mu  = sum * (1.f/192.f);
    float var = sq * (1.f/192.f) - mu*mu;
    float inv = rsqrtf(var + 1e-5f);
    float* op = out + (size_t)r*D + hh*DH;
    #pragma unroll
    for (int k = 0; k < 6; k++)
        op[lane + 32*k] = (v[k] - mu) * inv * gscale[hh*DH + lane + 32*k];
}

// =====================================================================
extern "C" void kernel_launch(void* const* d_in, const int* in_sizes, int n_in,
                              void* d_out, int out_size)
{
    const float* x     = (const float*)d_in[0];
    const float* ck    = (const float*)d_in[1];
    const float* cb    = (const float*)d_in[2];
    const float* Wi    = (const float*)d_in[3];
    const float* Wf    = (const float*)d_in[4];
    const float* Wz    = (const float*)d_in[5];
    const float* Wo    = (const float*)d_in[6];
    const float* R     = (const float*)d_in[7];
    const float* cbias = (const float*)d_in[8];
    const float* gs    = (const float*)d_in[9];
    float* out = (float*)d_out;

    conv_swish_kernel<<<(B*S*D + 255)/256, 256>>>(x, ck, cb);

    size_t gemm_smem = (size_t)(192*192 + GT_ROWS*IPAD) * sizeof(float);
    cudaFuncSetAttribute(gate_gemm_kernel,
                         cudaFuncAttributeMaxDynamicSharedMemorySize, (int)gemm_smem);
    dim3 ggrid(BS/GT_ROWS, NH, 4);
    gate_gemm_kernel<<<ggrid, 256, gemm_smem>>>(x, Wi, Wf, Wz, Wo, cbias);

    scan_kernel<<<128, 192>>>(R);

    ln_kernel<<<(BS*NH*32 + 255)/256, 256>>>(gs, out);
}